// round 1
// baseline (speedup 1.0000x reference)
#include <cuda_runtime.h>

// SNNModel: 3-layer LIF SNN, T=10 steps.
// B=1024, D=4000, H=2048, O=1000, chunk=400.
// Key algebraic optimization: prefix-masked x @ W1 at step t equals a running
// accumulation of per-chunk partial GEMMs -> 10x fewer layer-1 FLOPs.

namespace {
constexpr int kB = 1024;
constexpr int kD = 4000;
constexpr int kH = 2048;
constexpr int kO = 1000;
constexpr int kT = 10;
constexpr int kChunk = 400;
}

// Persistent state (device globals: no allocation allowed in kernel_launch).
__device__ float g_v1[kB * kH];
__device__ float g_v2[kB * kH];
__device__ float g_v3[kB * kO];
__device__ float g_acc1[kB * kH];
__device__ float g_s1[kB * kH];
__device__ float g_s2[kB * kH];
__device__ float g_s3[kB * kO];   // scratch sink for non-final layer-3 spikes

__global__ void init_state() {
    int stride = gridDim.x * blockDim.x;
    int i0 = blockIdx.x * blockDim.x + threadIdx.x;
    for (int i = i0; i < kB * kH; i += stride) {
        g_v1[i] = 0.0f;
        g_v2[i] = 0.0f;
        g_acc1[i] = 0.0f;
    }
    for (int i = i0; i < kB * kO; i += stride) {
        g_v3[i] = 0.0f;
    }
}

// Fused GEMM + LIF epilogue.
//   sum = A[M x K] @ W[K x N]      (A row-major lda, W row-major ldb)
//   MODE 0 (layer 1): accNew = accbuf + sum; accbuf = accNew; c = accNew + bias
//   MODE 1          : c = sum + bias
//   LIF: v = v + (c - v) * 0.5;  s = (v >= 1) ? 1 : 0;  v *= (1 - s)
// M is always 1024 (divisible by BM); K always divisible by 8; N may be ragged.
template <int MODE>
__global__ __launch_bounds__(256, 1) void gemm_lif(
    const float* __restrict__ A, const float* __restrict__ W,
    const float* __restrict__ bias,
    float* __restrict__ vstate, float* __restrict__ sout,
    float* __restrict__ accbuf,
    int N, int K, int lda, int ldb)
{
    constexpr int BM = 128, BN = 128, BK = 8;
    __shared__ float As[BK][BM];
    __shared__ float Bs[BK][BN];

    const int tid = threadIdx.x;
    const int m0 = blockIdx.y * BM;
    const int n0 = blockIdx.x * BN;

    // compute-thread mapping: 16x16 threads, 8x8 outputs each
    const int trow = tid >> 4;        // 0..15
    const int tcol = tid & 15;        // 0..15

    // A-tile load mapping: 128 rows x 8 k, float4 along k (2 per row)
    const int aRow = tid >> 1;        // 0..127
    const int aQ = (tid & 1) * 4;     // 0 or 4
    // B-tile load mapping: 8 k-rows x 128 n, float4 along n
    const int bRow = tid >> 5;        // 0..7
    const int bCol = (tid & 31) * 4;  // 0..124

    const float* Aptr = A + (long)(m0 + aRow) * lda + aQ;
    const float* Wptr = W + (long)bRow * ldb + n0 + bCol;
    const bool bVecOK = (n0 + bCol + 3) < N;

    float acc[8][8];
#pragma unroll
    for (int i = 0; i < 8; i++)
#pragma unroll
        for (int j = 0; j < 8; j++) acc[i][j] = 0.0f;

    for (int k0 = 0; k0 < K; k0 += BK) {
        // load A tile (transposed into smem)
        float4 av = *reinterpret_cast<const float4*>(Aptr + k0);
        As[aQ + 0][aRow] = av.x;
        As[aQ + 1][aRow] = av.y;
        As[aQ + 2][aRow] = av.z;
        As[aQ + 3][aRow] = av.w;
        // load B tile
        const float* wp = Wptr + (long)k0 * ldb;
        if (bVecOK) {
            *reinterpret_cast<float4*>(&Bs[bRow][bCol]) =
                *reinterpret_cast<const float4*>(wp);
        } else {
#pragma unroll
            for (int q = 0; q < 4; q++)
                Bs[bRow][bCol + q] = (n0 + bCol + q < N) ? wp[q] : 0.0f;
        }
        __syncthreads();

#pragma unroll
        for (int kk = 0; kk < BK; kk++) {
            float af[8], bf[8];
            *reinterpret_cast<float4*>(&af[0]) =
                *reinterpret_cast<const float4*>(&As[kk][trow * 8]);
            *reinterpret_cast<float4*>(&af[4]) =
                *reinterpret_cast<const float4*>(&As[kk][trow * 8 + 4]);
            *reinterpret_cast<float4*>(&bf[0]) =
                *reinterpret_cast<const float4*>(&Bs[kk][tcol * 8]);
            *reinterpret_cast<float4*>(&bf[4]) =
                *reinterpret_cast<const float4*>(&Bs[kk][tcol * 8 + 4]);
#pragma unroll
            for (int i = 0; i < 8; i++)
#pragma unroll
                for (int j = 0; j < 8; j++)
                    acc[i][j] = fmaf(af[i], bf[j], acc[i][j]);
        }
        __syncthreads();
    }

    // fused LIF epilogue
#pragma unroll
    for (int i = 0; i < 8; i++) {
        const int r = m0 + trow * 8 + i;
#pragma unroll
        for (int j = 0; j < 8; j++) {
            const int c = n0 + tcol * 8 + j;
            if (c < N) {
                const int idx = r * N + c;
                float cc;
                if (MODE == 0) {
                    float an = accbuf[idx] + acc[i][j];
                    accbuf[idx] = an;
                    cc = an + bias[c];
                } else {
                    cc = acc[i][j] + bias[c];
                }
                float v = vstate[idx];
                v = v + (cc - v) * 0.5f;          // matches reference formula
                float s = (v >= 1.0f) ? 1.0f : 0.0f;
                vstate[idx] = v * (1.0f - s);     // hard reset
                sout[idx] = s;
            }
        }
    }
}

extern "C" void kernel_launch(void* const* d_in, const int* in_sizes, int n_in,
                              void* d_out, int out_size) {
    const float* x  = (const float*)d_in[0];
    const float* W1 = (const float*)d_in[1];
    const float* b1 = (const float*)d_in[2];
    const float* W2 = (const float*)d_in[3];
    const float* b2 = (const float*)d_in[4];
    const float* W3 = (const float*)d_in[5];
    const float* b3 = (const float*)d_in[6];
    float* out = (float*)d_out;

    float *v1, *v2, *v3, *acc1, *s1, *s2, *s3;
    cudaGetSymbolAddress((void**)&v1, g_v1);
    cudaGetSymbolAddress((void**)&v2, g_v2);
    cudaGetSymbolAddress((void**)&v3, g_v3);
    cudaGetSymbolAddress((void**)&acc1, g_acc1);
    cudaGetSymbolAddress((void**)&s1, g_s1);
    cudaGetSymbolAddress((void**)&s2, g_s2);
    cudaGetSymbolAddress((void**)&s3, g_s3);

    init_state<<<512, 256>>>();

    dim3 blk(256);
    dim3 gridH(kH / 128, kB / 128);           // 16 x 8
    dim3 gridO((kO + 127) / 128, kB / 128);   // 8 x 8

    for (int t = 0; t < kT; t++) {
        // layer 1: incremental chunk GEMM into running accumulator + LIF
        gemm_lif<0><<<gridH, blk>>>(
            x + t * kChunk, W1 + (long)t * kChunk * kH, b1,
            v1, s1, acc1, kH, kChunk, kD, kH);
        // layer 2
        gemm_lif<1><<<gridH, blk>>>(
            s1, W2, b2, v2, s2, nullptr, kH, kH, kH, kH);
        // layer 3 (spikes only matter at the final step)
        gemm_lif<1><<<gridO, blk>>>(
            s2, W3, b3, v3, (t == kT - 1) ? out : s3, nullptr,
            kO, kH, kH, kO);
    }
}

// round 3
// speedup vs baseline: 3.0659x; 3.0659x over previous
#include <cuda_runtime.h>
#include <cuda_bf16.h>
#include <cstdint>

// SNNModel: 3-layer LIF SNN, T=10. B=1024, D=4000, H=2048, O=1000.
// Tensor-core path via mma.sync (HMMA, bf16 in / fp32 accum) since tcgen05 is
// not available under the harness's .target sm_103.
//   L2/L3: binary A (spikes) exact in bf16; W = Wh+Wm+Wl 3-split, K-concat (K'=6144).
//   L1: x = xh+xl, W1 = wh+wm+wl; 5 cross terms materialized as K'=2048 padded segments.

namespace {
constexpr int kB = 1024, kD = 4000, kH = 2048, kO = 1000, kT = 10;
constexpr int kK1  = 2048;        // per-step padded K' for layer 1 (5*400 -> 2048)
constexpr int kLd1 = kT * kK1;    // 20480
constexpr int kK2  = 3 * kH;      // 6144
constexpr int kOp  = 1024;        // padded N rows for W3cat
constexpr unsigned kSmemBytes = 65536u;   // 2 x (16KB A + 16KB W); epilogue reuses as 128x128 f32
}

// ---------------- persistent device buffers ----------------
__device__ __align__(16) float g_v1[kB * kH];
__device__ __align__(16) float g_v2[kB * kH];
__device__ __align__(16) float g_v3[kB * kO];
__device__ __align__(16) float g_acc1[kB * kH];
__device__ __align__(16) __nv_bfloat16 g_s1[kB * kH];
__device__ __align__(16) __nv_bfloat16 g_s2[kB * kH];
__device__ __align__(16) __nv_bfloat16 g_A1c[(size_t)kB * kLd1];   // [B, 10*2048]
__device__ __align__(16) __nv_bfloat16 g_W1c[(size_t)kH * kLd1];   // [H, 10*2048] (N-major, K contig)
__device__ __align__(16) __nv_bfloat16 g_W2c[(size_t)kH * kK2];    // [H, 6144]
__device__ __align__(16) __nv_bfloat16 g_W3c[(size_t)kOp * kK2];   // [1024, 6144]

// ---------------- PTX helpers ----------------
__device__ __forceinline__ uint32_t smem_u32(const void* p) {
    uint32_t a;
    asm("{ .reg .u64 t; cvta.to.shared.u64 t, %1; cvt.u32.u64 %0, t; }" : "=r"(a) : "l"(p));
    return a;
}
__device__ __forceinline__ void cp16(uint32_t dst, const void* src) {
    asm volatile("cp.async.cg.shared.global [%0], [%1], 16;" :: "r"(dst), "l"(src));
}
__device__ __forceinline__ void cp_commit() { asm volatile("cp.async.commit_group;" ::: "memory"); }
__device__ __forceinline__ void cp_wait1()  { asm volatile("cp.async.wait_group 1;" ::: "memory"); }
__device__ __forceinline__ void cp_wait0()  { asm volatile("cp.async.wait_group 0;" ::: "memory"); }
__device__ __forceinline__ void ldmx4(uint32_t& r0, uint32_t& r1, uint32_t& r2, uint32_t& r3,
                                      uint32_t addr) {
    asm volatile("ldmatrix.sync.aligned.m8n8.x4.shared.b16 {%0,%1,%2,%3}, [%4];"
                 : "=r"(r0), "=r"(r1), "=r"(r2), "=r"(r3) : "r"(addr));
}
__device__ __forceinline__ void mma16816(float& c0, float& c1, float& c2, float& c3,
                                         uint32_t a0, uint32_t a1, uint32_t a2, uint32_t a3,
                                         uint32_t b0, uint32_t b1) {
    asm volatile(
        "mma.sync.aligned.m16n8k16.row.col.f32.bf16.bf16.f32 "
        "{%0,%1,%2,%3}, {%4,%5,%6,%7}, {%8,%9}, {%0,%1,%2,%3};"
        : "+f"(c0), "+f"(c1), "+f"(c2), "+f"(c3)
        : "r"(a0), "r"(a1), "r"(a2), "r"(a3), "r"(b0), "r"(b1));
}
__device__ __forceinline__ uint32_t sw128(uint32_t off) {
    return off ^ ((off >> 3) & 0x70);
}

// ---------------- init / precompute kernels ----------------
__global__ void init_state() {
    int stride = gridDim.x * blockDim.x;
    int i0 = blockIdx.x * blockDim.x + threadIdx.x;
    for (int i = i0; i < kB * kH; i += stride) {
        g_v1[i] = 0.0f; g_v2[i] = 0.0f; g_acc1[i] = 0.0f;
    }
    for (int i = i0; i < kB * kO; i += stride) g_v3[i] = 0.0f;
}

// A1cat[m, t*2048 + j] : j<2000 -> seg=j/400 (0..2: xh, 3..4: xl) of x[m, t*400 + j%400]; else 0
__global__ void build_xcat(const float* __restrict__ x) {
    long idx = (long)blockIdx.x * blockDim.x + threadIdx.x;
    if (idx >= (long)kB * kLd1) return;
    int m = (int)(idx / kLd1), c = (int)(idx % kLd1);
    int t = c / kK1, j = c % kK1;
    __nv_bfloat16 o = __float2bfloat16(0.0f);
    if (j < 2000) {
        int seg = j / 400, kk = j % 400;
        float xv = x[(long)m * kD + t * 400 + kk];
        __nv_bfloat16 h = __float2bfloat16(xv);
        o = (seg < 3) ? h : __float2bfloat16(xv - __bfloat162float(h));
    }
    g_A1c[idx] = o;
}

// W1cat: per step block [wh | wm | wl | wh | wm] (each 400) + 48 pad
__global__ void build_w1(const float* __restrict__ W) {   // W: [4000, 2048]
    __shared__ float tile[32][33];
    int k0 = blockIdx.x * 32, n0 = blockIdx.y * 32;
    int tx = threadIdx.x & 31, ty = threadIdx.x >> 5;
    for (int i = 0; i < 32; i += 8)
        tile[ty + i][tx] = W[(long)(k0 + ty + i) * kH + n0 + tx];
    __syncthreads();
    for (int i = 0; i < 32; i += 8) {
        int n = n0 + ty + i, kg = k0 + tx;
        int t = kg / 400, kk = kg % 400;
        float v = tile[tx][ty + i];
        __nv_bfloat16 h = __float2bfloat16(v);
        float r = v - __bfloat162float(h);
        __nv_bfloat16 mm = __float2bfloat16(r);
        __nv_bfloat16 l = __float2bfloat16(r - __bfloat162float(mm));
        long base = (long)n * kLd1 + (long)t * kK1;
        g_W1c[base + kk]        = h;
        g_W1c[base + 1200 + kk] = h;
        g_W1c[base + 400 + kk]  = mm;
        g_W1c[base + 1600 + kk] = mm;
        g_W1c[base + 800 + kk]  = l;
    }
}
__global__ void pad_w1() {   // zero cols [2000,2048) of every step block
    long idx = (long)blockIdx.x * blockDim.x + threadIdx.x;   // kH * 10 * 48
    if (idx >= (long)kH * 480) return;
    int n = (int)(idx / 480), r = (int)(idx % 480);
    int t = r / 48, j = 2000 + r % 48;
    g_W1c[(long)n * kLd1 + (long)t * kK1 + j] = __float2bfloat16(0.0f);
}

__global__ void build_w2(const float* __restrict__ W) {   // [2048,2048] -> [2048, 6144]
    __shared__ float tile[32][33];
    int k0 = blockIdx.x * 32, n0 = blockIdx.y * 32;
    int tx = threadIdx.x & 31, ty = threadIdx.x >> 5;
    for (int i = 0; i < 32; i += 8)
        tile[ty + i][tx] = W[(long)(k0 + ty + i) * kH + n0 + tx];
    __syncthreads();
    for (int i = 0; i < 32; i += 8) {
        int n = n0 + ty + i, k = k0 + tx;
        float v = tile[tx][ty + i];
        __nv_bfloat16 h = __float2bfloat16(v);
        float r = v - __bfloat162float(h);
        __nv_bfloat16 mm = __float2bfloat16(r);
        __nv_bfloat16 l = __float2bfloat16(r - __bfloat162float(mm));
        long base = (long)n * kK2;
        g_W2c[base + k] = h; g_W2c[base + kH + k] = mm; g_W2c[base + 2 * kH + k] = l;
    }
}

__global__ void build_w3(const float* __restrict__ W) {   // [2048,1000] -> [1024, 6144]
    __shared__ float tile[32][33];
    int k0 = blockIdx.x * 32, n0 = blockIdx.y * 32;
    int tx = threadIdx.x & 31, ty = threadIdx.x >> 5;
    for (int i = 0; i < 32; i += 8) {
        int n = n0 + tx;
        tile[ty + i][tx] = (n < kO) ? W[(long)(k0 + ty + i) * kO + n] : 0.0f;
    }
    __syncthreads();
    for (int i = 0; i < 32; i += 8) {
        int n = n0 + ty + i, k = k0 + tx;
        float v = tile[tx][ty + i];
        __nv_bfloat16 h = __float2bfloat16(v);
        float r = v - __bfloat162float(h);
        __nv_bfloat16 mm = __float2bfloat16(r);
        __nv_bfloat16 l = __float2bfloat16(r - __bfloat162float(mm));
        long base = (long)n * kK2;
        g_W3c[base + k] = h; g_W3c[base + kH + k] = mm; g_W3c[base + 2 * kH + k] = l;
    }
}

// ---------------- main HMMA GEMM + LIF kernel ----------------
// D[128x128] tile = A[m0:,:K'] @ Wc[n0:,:K']^T, A k-index wraps mod 2048.
__global__ __launch_bounds__(256) void snn_mma(
    const __nv_bfloat16* __restrict__ A, long lda,
    const __nv_bfloat16* __restrict__ Wc, long ldw,
    int Kp,
    const float* __restrict__ bias,
    float* __restrict__ vstate,
    float* __restrict__ acc,                 // nullable (layer-1 running accumulator)
    __nv_bfloat16* __restrict__ sout_bf,     // nullable
    float* __restrict__ sout_f,              // nullable
    int N)
{
    extern __shared__ __align__(1024) char smem[];
    const uint32_t sbase = smem_u32(smem);
    const int tid = threadIdx.x, wid = tid >> 5, lid = tid & 31;
    const int m0 = blockIdx.y * 128, n0 = blockIdx.x * 128;
    const int wm = (wid >> 2) * 64;          // warp m offset (0 or 64)
    const int wn = (wid & 3) * 32;           // warp n offset (0,32,64,96)

    const int NC = Kp / 64;

    float accf[4][4][4];
#pragma unroll
    for (int i = 0; i < 4; i++)
#pragma unroll
        for (int j = 0; j < 4; j++)
#pragma unroll
            for (int q = 0; q < 4; q++) accf[i][j][q] = 0.0f;

    auto load_chunk = [&](int c, int b) {
        const int k0 = c * 64;
        const int ak = k0 & 2047;
        const uint32_t abuf = sbase + b * 32768;
        const uint32_t wbuf = abuf + 16384;
#pragma unroll
        for (int p = 0; p < 4; p++) {
            int off = (p * 256 + tid) * 16;
            int row = off >> 7, colb = off & 127;
            cp16(abuf + sw128(off), A + (long)(m0 + row) * lda + ak + (colb >> 1));
        }
#pragma unroll
        for (int p = 0; p < 4; p++) {
            int off = (p * 256 + tid) * 16;
            int row = off >> 7, colb = off & 127;
            cp16(wbuf + sw128(off), Wc + (long)(n0 + row) * ldw + k0 + (colb >> 1));
        }
        cp_commit();
    };

    // per-lane ldmatrix address components
    const int a_r = (lid & 7) + ((lid >> 3) & 1) * 8;   // row within 16-row A block
    const int a_k = (lid >> 4) * 16;                    // byte offset within 32B k-slice
    const int b_r = (lid & 7) + (lid >> 4) * 8;         // row within 16-row W block
    const int b_k = ((lid >> 3) & 1) * 16;

    load_chunk(0, 0);

    for (int c = 0; c < NC; c++) {
        const int b = c & 1;
        if (c + 1 < NC) { load_chunk(c + 1, b ^ 1); cp_wait1(); }
        else            { cp_wait0(); }
        __syncthreads();

        const uint32_t abuf = sbase + b * 32768;
        const uint32_t wbuf = abuf + 16384;
#pragma unroll
        for (int ks = 0; ks < 4; ks++) {
            uint32_t af[4][4];
#pragma unroll
            for (int mi = 0; mi < 4; mi++) {
                uint32_t off = (uint32_t)((wm + mi * 16 + a_r) * 128 + ks * 32 + a_k);
                ldmx4(af[mi][0], af[mi][1], af[mi][2], af[mi][3], abuf + sw128(off));
            }
            uint32_t bf[2][4];
#pragma unroll
            for (int np = 0; np < 2; np++) {
                uint32_t off = (uint32_t)((wn + np * 16 + b_r) * 128 + ks * 32 + b_k);
                ldmx4(bf[np][0], bf[np][1], bf[np][2], bf[np][3], wbuf + sw128(off));
            }
#pragma unroll
            for (int mi = 0; mi < 4; mi++)
#pragma unroll
                for (int ni = 0; ni < 4; ni++) {
                    const uint32_t* bp = &bf[ni >> 1][(ni & 1) * 2];
                    mma16816(accf[mi][ni][0], accf[mi][ni][1], accf[mi][ni][2], accf[mi][ni][3],
                             af[mi][0], af[mi][1], af[mi][2], af[mi][3], bp[0], bp[1]);
                }
        }
        __syncthreads();
    }

    // epilogue part 1: accumulators -> smem fp32 [128][128]
    {
        float* Ds = reinterpret_cast<float*>(smem);
        const int g = lid >> 2, tg = lid & 3;
#pragma unroll
        for (int mi = 0; mi < 4; mi++) {
#pragma unroll
            for (int ni = 0; ni < 4; ni++) {
                int row = wm + mi * 16 + g;
                int col = wn + ni * 8 + tg * 2;
                Ds[row * 128 + col]       = accf[mi][ni][0];
                Ds[row * 128 + col + 1]   = accf[mi][ni][1];
                Ds[(row + 8) * 128 + col]     = accf[mi][ni][2];
                Ds[(row + 8) * 128 + col + 1] = accf[mi][ni][3];
            }
        }
    }
    __syncthreads();

    // epilogue part 2: coalesced LIF RMW
    {
        float* Ds = reinterpret_cast<float*>(smem);
        int ncols = N - n0; if (ncols > 128) ncols = 128;
#pragma unroll 4
        for (int p = 0; p < 16; p++) {
            int i4 = p * 256 + tid;
            int row = i4 >> 5, col = (i4 & 31) * 4;
            if (col < ncols) {
                long gidx = (long)(m0 + row) * N + n0 + col;
                float4 d = *reinterpret_cast<float4*>(&Ds[row * 128 + col]);
                if (acc) {
                    float4 a = *reinterpret_cast<const float4*>(&acc[gidx]);
                    d.x += a.x; d.y += a.y; d.z += a.z; d.w += a.w;
                    *reinterpret_cast<float4*>(&acc[gidx]) = d;
                }
                float4 bb = *reinterpret_cast<const float4*>(&bias[n0 + col]);
                float4 vo = *reinterpret_cast<float4*>(&vstate[gidx]);
                float cc, v, s[4];
                cc = d.x + bb.x; v = vo.x + (cc - vo.x) * 0.5f; s[0] = (v >= 1.0f) ? 1.0f : 0.0f; vo.x = v * (1.0f - s[0]);
                cc = d.y + bb.y; v = vo.y + (cc - vo.y) * 0.5f; s[1] = (v >= 1.0f) ? 1.0f : 0.0f; vo.y = v * (1.0f - s[1]);
                cc = d.z + bb.z; v = vo.z + (cc - vo.z) * 0.5f; s[2] = (v >= 1.0f) ? 1.0f : 0.0f; vo.z = v * (1.0f - s[2]);
                cc = d.w + bb.w; v = vo.w + (cc - vo.w) * 0.5f; s[3] = (v >= 1.0f) ? 1.0f : 0.0f; vo.w = v * (1.0f - s[3]);
                *reinterpret_cast<float4*>(&vstate[gidx]) = vo;
                if (sout_bf) {
                    __nv_bfloat162 h0 = __floats2bfloat162_rn(s[0], s[1]);
                    __nv_bfloat162 h1 = __floats2bfloat162_rn(s[2], s[3]);
                    *reinterpret_cast<__nv_bfloat162*>(&sout_bf[gidx]) = h0;
                    *reinterpret_cast<__nv_bfloat162*>(&sout_bf[gidx + 2]) = h1;
                }
                if (sout_f) {
                    float4 so; so.x = s[0]; so.y = s[1]; so.z = s[2]; so.w = s[3];
                    *reinterpret_cast<float4*>(&sout_f[gidx]) = so;
                }
            }
        }
    }
}

// ---------------- launch ----------------
extern "C" void kernel_launch(void* const* d_in, const int* in_sizes, int n_in,
                              void* d_out, int out_size) {
    const float* x  = (const float*)d_in[0];
    const float* W1 = (const float*)d_in[1];
    const float* b1 = (const float*)d_in[2];
    const float* W2 = (const float*)d_in[3];
    const float* b2 = (const float*)d_in[4];
    const float* W3 = (const float*)d_in[5];
    const float* b3 = (const float*)d_in[6];
    float* out = (float*)d_out;

    float *v1, *v2, *v3, *acc1;
    __nv_bfloat16 *s1, *s2, *a1c, *w1c, *w2c, *w3c;
    cudaGetSymbolAddress((void**)&v1, g_v1);
    cudaGetSymbolAddress((void**)&v2, g_v2);
    cudaGetSymbolAddress((void**)&v3, g_v3);
    cudaGetSymbolAddress((void**)&acc1, g_acc1);
    cudaGetSymbolAddress((void**)&s1, g_s1);
    cudaGetSymbolAddress((void**)&s2, g_s2);
    cudaGetSymbolAddress((void**)&a1c, g_A1c);
    cudaGetSymbolAddress((void**)&w1c, g_W1c);
    cudaGetSymbolAddress((void**)&w2c, g_W2c);
    cudaGetSymbolAddress((void**)&w3c, g_W3c);

    cudaFuncSetAttribute(snn_mma, cudaFuncAttributeMaxDynamicSharedMemorySize, kSmemBytes);

    init_state<<<512, 256>>>();
    build_xcat<<<(int)(((long)kB * kLd1) / 256), 256>>>(x);
    build_w1<<<dim3(125, 64), 256>>>(W1);
    pad_w1<<<3840, 256>>>();
    build_w2<<<dim3(64, 64), 256>>>(W2);
    build_w3<<<dim3(64, 32), 256>>>(W3);

    dim3 blk(256);
    dim3 gridH(16, 8);   // N=2048 tiles x M=1024 tiles
    dim3 gridO(8, 8);    // N=1000 -> 8 tiles of 128

    for (int t = 0; t < kT; t++) {
        snn_mma<<<gridH, blk, kSmemBytes>>>(
            a1c + (long)t * kK1, kLd1, w1c + (long)t * kK1, kLd1, kK1,
            b1, v1, acc1, s1, nullptr, kH);
        snn_mma<<<gridH, blk, kSmemBytes>>>(
            s1, kH, w2c, kK2, kK2,
            b2, v2, nullptr, s2, nullptr, kH);
        snn_mma<<<gridO, blk, kSmemBytes>>>(
            s2, kH, w3c, kK2, kK2,
            b3, v3, nullptr, nullptr, (t == kT - 1) ? out : nullptr, kO);
    }
}

// round 4
// speedup vs baseline: 5.1453x; 1.6782x over previous
#include <cuda_runtime.h>
#include <cuda_fp16.h>
#include <cstdint>

// SNNModel: 3-layer LIF SNN, T=10. B=1024, D=4000, H=2048, O=1000.
// HMMA (mma.sync m16n8k16, fp16 in / fp32 accum) with split-precision weights:
//   L2/L3: binary spikes exact in fp16; W = Wh+Wl fp16 2-split, K-concat K'=4096.
//   L1: x=xh+xl, W1=wh+wl; 3 cross terms (xh*wh, xh*wl, xl*wh), K'=1280.
// Residual error ~2^-22 relative, far below observed spike-threshold margins.

namespace {
constexpr int kB = 1024, kD = 4000, kH = 2048, kO = 1000, kT = 10;
constexpr int kK1  = 1280;        // per-step padded K' for layer 1 (3*400 -> 1280)
constexpr int kLd1 = kT * kK1;    // 12800
constexpr int kK2  = 2 * kH;      // 4096
constexpr int kOp  = 1024;        // padded N rows for W3cat
constexpr unsigned kSmemBytes = 65536u;
}

// ---------------- persistent device buffers ----------------
__device__ __align__(16) float g_v1[kB * kH];
__device__ __align__(16) float g_v2[kB * kH];
__device__ __align__(16) float g_v3[kB * kO];
__device__ __align__(16) float g_acc1[kB * kH];
__device__ __align__(16) __half g_s1[kB * kH];
__device__ __align__(16) __half g_s2[kB * kH];
__device__ __align__(16) __half g_A1c[(size_t)kB * kLd1];   // [B, 10*1280]
__device__ __align__(16) __half g_W1c[(size_t)kH * kLd1];   // [H, 10*1280] (N-major, K contig)
__device__ __align__(16) __half g_W2c[(size_t)kH * kK2];    // [H, 4096]
__device__ __align__(16) __half g_W3c[(size_t)kOp * kK2];   // [1024, 4096]

// ---------------- PTX helpers ----------------
__device__ __forceinline__ uint32_t smem_u32(const void* p) {
    uint32_t a;
    asm("{ .reg .u64 t; cvta.to.shared.u64 t, %1; cvt.u32.u64 %0, t; }" : "=r"(a) : "l"(p));
    return a;
}
__device__ __forceinline__ void cp16(uint32_t dst, const void* src) {
    asm volatile("cp.async.cg.shared.global [%0], [%1], 16;" :: "r"(dst), "l"(src));
}
__device__ __forceinline__ void cp_commit() { asm volatile("cp.async.commit_group;" ::: "memory"); }
__device__ __forceinline__ void cp_wait1()  { asm volatile("cp.async.wait_group 1;" ::: "memory"); }
__device__ __forceinline__ void cp_wait0()  { asm volatile("cp.async.wait_group 0;" ::: "memory"); }
__device__ __forceinline__ void ldmx4(uint32_t& r0, uint32_t& r1, uint32_t& r2, uint32_t& r3,
                                      uint32_t addr) {
    asm volatile("ldmatrix.sync.aligned.m8n8.x4.shared.b16 {%0,%1,%2,%3}, [%4];"
                 : "=r"(r0), "=r"(r1), "=r"(r2), "=r"(r3) : "r"(addr));
}
__device__ __forceinline__ void mma16816(float& c0, float& c1, float& c2, float& c3,
                                         uint32_t a0, uint32_t a1, uint32_t a2, uint32_t a3,
                                         uint32_t b0, uint32_t b1) {
    asm volatile(
        "mma.sync.aligned.m16n8k16.row.col.f32.f16.f16.f32 "
        "{%0,%1,%2,%3}, {%4,%5,%6,%7}, {%8,%9}, {%0,%1,%2,%3};"
        : "+f"(c0), "+f"(c1), "+f"(c2), "+f"(c3)
        : "r"(a0), "r"(a1), "r"(a2), "r"(a3), "r"(b0), "r"(b1));
}
__device__ __forceinline__ uint32_t sw128(uint32_t off) {
    return off ^ ((off >> 3) & 0x70);
}

// ---------------- init / precompute kernels ----------------
__global__ void init_state() {
    int stride = gridDim.x * blockDim.x;
    int i0 = blockIdx.x * blockDim.x + threadIdx.x;
    for (int i = i0; i < kB * kH; i += stride) {
        g_v1[i] = 0.0f; g_v2[i] = 0.0f; g_acc1[i] = 0.0f;
    }
    for (int i = i0; i < kB * kO; i += stride) g_v3[i] = 0.0f;
}

// A1cat[m, t*1280 + j] : j<1200 -> seg=j/400 (0,1: xh; 2: xl) of x[m, t*400 + j%400]; else 0
__global__ void build_xcat(const float* __restrict__ x) {
    long idx = (long)blockIdx.x * blockDim.x + threadIdx.x;
    if (idx >= (long)kB * kLd1) return;
    int m = (int)(idx / kLd1), c = (int)(idx % kLd1);
    int t = c / kK1, j = c % kK1;
    __half o = __float2half_rn(0.0f);
    if (j < 1200) {
        int seg = j / 400, kk = j % 400;
        float xv = x[(long)m * kD + t * 400 + kk];
        __half h = __float2half_rn(xv);
        o = (seg < 2) ? h : __float2half_rn(xv - __half2float(h));
    }
    g_A1c[idx] = o;
}

// W1cat: per step block [wh | wl | wh] (each 400) + 80 pad. Pairs: xh*wh, xh*wl, xl*wh.
__global__ void build_w1(const float* __restrict__ W) {   // W: [4000, 2048]
    __shared__ float tile[32][33];
    int k0 = blockIdx.x * 32, n0 = blockIdx.y * 32;
    int tx = threadIdx.x & 31, ty = threadIdx.x >> 5;
    for (int i = 0; i < 32; i += 8)
        tile[ty + i][tx] = W[(long)(k0 + ty + i) * kH + n0 + tx];
    __syncthreads();
    for (int i = 0; i < 32; i += 8) {
        int n = n0 + ty + i, kg = k0 + tx;
        int t = kg / 400, kk = kg % 400;
        float v = tile[tx][ty + i];
        __half h = __float2half_rn(v);
        __half l = __float2half_rn(v - __half2float(h));
        long base = (long)n * kLd1 + (long)t * kK1;
        g_W1c[base + kk]       = h;
        g_W1c[base + 800 + kk] = h;
        g_W1c[base + 400 + kk] = l;
    }
}
__global__ void pad_w1() {   // zero cols [1200,1280) of every step block
    long idx = (long)blockIdx.x * blockDim.x + threadIdx.x;   // kH * 10 * 80
    if (idx >= (long)kH * 800) return;
    int n = (int)(idx / 800), r = (int)(idx % 800);
    int t = r / 80, j = 1200 + r % 80;
    g_W1c[(long)n * kLd1 + (long)t * kK1 + j] = __float2half_rn(0.0f);
}

__global__ void build_w2(const float* __restrict__ W) {   // [2048,2048] -> [2048, 4096]
    __shared__ float tile[32][33];
    int k0 = blockIdx.x * 32, n0 = blockIdx.y * 32;
    int tx = threadIdx.x & 31, ty = threadIdx.x >> 5;
    for (int i = 0; i < 32; i += 8)
        tile[ty + i][tx] = W[(long)(k0 + ty + i) * kH + n0 + tx];
    __syncthreads();
    for (int i = 0; i < 32; i += 8) {
        int n = n0 + ty + i, k = k0 + tx;
        float v = tile[tx][ty + i];
        __half h = __float2half_rn(v);
        __half l = __float2half_rn(v - __half2float(h));
        long base = (long)n * kK2;
        g_W2c[base + k] = h; g_W2c[base + kH + k] = l;
    }
}

__global__ void build_w3(const float* __restrict__ W) {   // [2048,1000] -> [1024, 4096]
    __shared__ float tile[32][33];
    int k0 = blockIdx.x * 32, n0 = blockIdx.y * 32;
    int tx = threadIdx.x & 31, ty = threadIdx.x >> 5;
    for (int i = 0; i < 32; i += 8) {
        int n = n0 + tx;
        tile[ty + i][tx] = (n < kO) ? W[(long)(k0 + ty + i) * kO + n] : 0.0f;
    }
    __syncthreads();
    for (int i = 0; i < 32; i += 8) {
        int n = n0 + ty + i, k = k0 + tx;
        float v = tile[tx][ty + i];
        __half h = __float2half_rn(v);
        __half l = __float2half_rn(v - __half2float(h));
        long base = (long)n * kK2;
        g_W3c[base + k] = h; g_W3c[base + kH + k] = l;
    }
}

// ---------------- main HMMA GEMM + LIF kernel ----------------
// D[BM x 128] tile = A[m0:,:K'] @ Wc[n0:,:K']^T, A k-index wraps mod 2048.
template <int BM>
__global__ __launch_bounds__(256) void snn_mma(
    const __half* __restrict__ A, long lda,
    const __half* __restrict__ Wc, long ldw,
    int Kp,
    const float* __restrict__ bias,
    float* __restrict__ vstate,
    float* __restrict__ acc,            // nullable (layer-1 running accumulator)
    __half* __restrict__ sout_h,        // nullable
    float* __restrict__ sout_f,         // nullable
    int N)
{
    constexpr int MI = BM / 32;                 // 16-row A blocks per warp
    constexpr uint32_t kABytes = BM * 128;      // A stage bytes
    constexpr uint32_t kStage = kABytes + 16384;

    extern __shared__ __align__(1024) char smem[];
    const uint32_t sbase = smem_u32(smem);
    const int tid = threadIdx.x, wid = tid >> 5, lid = tid & 31;
    const int m0 = blockIdx.y * BM, n0 = blockIdx.x * 128;
    const int wm = (wid >> 2) * (16 * MI);      // warp m offset
    const int wn = (wid & 3) * 32;              // warp n offset

    const int NC = Kp / 64;

    float accf[MI][4][4];
#pragma unroll
    for (int i = 0; i < MI; i++)
#pragma unroll
        for (int j = 0; j < 4; j++)
#pragma unroll
            for (int q = 0; q < 4; q++) accf[i][j][q] = 0.0f;

    auto load_chunk = [&](int c, int b) {
        const int k0 = c * 64;
        const int ak = k0 & 2047;               // A wraps mod 2048 (K-concat reuse)
        const uint32_t abuf = sbase + b * kStage;
        const uint32_t wbuf = abuf + kABytes;
#pragma unroll
        for (int p = 0; p < MI; p++) {
            int off = (p * 256 + tid) * 16;
            int row = off >> 7, colb = off & 127;
            cp16(abuf + sw128((uint32_t)off), A + (long)(m0 + row) * lda + ak + (colb >> 1));
        }
#pragma unroll
        for (int p = 0; p < 4; p++) {
            int off = (p * 256 + tid) * 16;
            int row = off >> 7, colb = off & 127;
            cp16(wbuf + sw128((uint32_t)off), Wc + (long)(n0 + row) * ldw + k0 + (colb >> 1));
        }
        cp_commit();
    };

    // per-lane ldmatrix address components
    const int a_r = (lid & 7) + ((lid >> 3) & 1) * 8;
    const int a_k = (lid >> 4) * 16;
    const int b_r = (lid & 7) + (lid >> 4) * 8;
    const int b_k = ((lid >> 3) & 1) * 16;

    load_chunk(0, 0);

    for (int c = 0; c < NC; c++) {
        const int b = c & 1;
        if (c + 1 < NC) { load_chunk(c + 1, b ^ 1); cp_wait1(); }
        else            { cp_wait0(); }
        __syncthreads();

        const uint32_t abuf = sbase + b * kStage;
        const uint32_t wbuf = abuf + kABytes;
#pragma unroll
        for (int ks = 0; ks < 4; ks++) {
            uint32_t af[MI][4];
#pragma unroll
            for (int mi = 0; mi < MI; mi++) {
                uint32_t off = (uint32_t)((wm + mi * 16 + a_r) * 128 + ks * 32 + a_k);
                ldmx4(af[mi][0], af[mi][1], af[mi][2], af[mi][3], abuf + sw128(off));
            }
            uint32_t bfr[2][4];
#pragma unroll
            for (int np = 0; np < 2; np++) {
                uint32_t off = (uint32_t)((wn + np * 16 + b_r) * 128 + ks * 32 + b_k);
                ldmx4(bfr[np][0], bfr[np][1], bfr[np][2], bfr[np][3], wbuf + sw128(off));
            }
#pragma unroll
            for (int mi = 0; mi < MI; mi++)
#pragma unroll
                for (int ni = 0; ni < 4; ni++) {
                    const uint32_t* bp = &bfr[ni >> 1][(ni & 1) * 2];
                    mma16816(accf[mi][ni][0], accf[mi][ni][1], accf[mi][ni][2], accf[mi][ni][3],
                             af[mi][0], af[mi][1], af[mi][2], af[mi][3], bp[0], bp[1]);
                }
        }
        __syncthreads();
    }

    // epilogue part 1: accumulators -> smem fp32 [BM][128]
    {
        float* Ds = reinterpret_cast<float*>(smem);
        const int g = lid >> 2, tg = lid & 3;
#pragma unroll
        for (int mi = 0; mi < MI; mi++) {
#pragma unroll
            for (int ni = 0; ni < 4; ni++) {
                int row = wm + mi * 16 + g;
                int col = wn + ni * 8 + tg * 2;
                Ds[row * 128 + col]           = accf[mi][ni][0];
                Ds[row * 128 + col + 1]       = accf[mi][ni][1];
                Ds[(row + 8) * 128 + col]     = accf[mi][ni][2];
                Ds[(row + 8) * 128 + col + 1] = accf[mi][ni][3];
            }
        }
    }
    __syncthreads();

    // epilogue part 2: coalesced LIF RMW
    {
        float* Ds = reinterpret_cast<float*>(smem);
        int ncols = N - n0; if (ncols > 128) ncols = 128;
#pragma unroll 4
        for (int p = 0; p < BM / 8; p++) {
            int i4 = p * 256 + tid;
            int row = i4 >> 5, col = (i4 & 31) * 4;
            if (col < ncols) {
                long gidx = (long)(m0 + row) * N + n0 + col;
                float4 d = *reinterpret_cast<float4*>(&Ds[row * 128 + col]);
                if (acc) {
                    float4 a = *reinterpret_cast<const float4*>(&acc[gidx]);
                    d.x += a.x; d.y += a.y; d.z += a.z; d.w += a.w;
                    *reinterpret_cast<float4*>(&acc[gidx]) = d;
                }
                float4 bb = *reinterpret_cast<const float4*>(&bias[n0 + col]);
                float4 vo = *reinterpret_cast<float4*>(&vstate[gidx]);
                float cc, v, s[4];
                cc = d.x + bb.x; v = vo.x + (cc - vo.x) * 0.5f; s[0] = (v >= 1.0f) ? 1.0f : 0.0f; vo.x = v * (1.0f - s[0]);
                cc = d.y + bb.y; v = vo.y + (cc - vo.y) * 0.5f; s[1] = (v >= 1.0f) ? 1.0f : 0.0f; vo.y = v * (1.0f - s[1]);
                cc = d.z + bb.z; v = vo.z + (cc - vo.z) * 0.5f; s[2] = (v >= 1.0f) ? 1.0f : 0.0f; vo.z = v * (1.0f - s[2]);
                cc = d.w + bb.w; v = vo.w + (cc - vo.w) * 0.5f; s[3] = (v >= 1.0f) ? 1.0f : 0.0f; vo.w = v * (1.0f - s[3]);
                *reinterpret_cast<float4*>(&vstate[gidx]) = vo;
                if (sout_h) {
                    __half2 h0 = __floats2half2_rn(s[0], s[1]);
                    __half2 h1 = __floats2half2_rn(s[2], s[3]);
                    *reinterpret_cast<__half2*>(&sout_h[gidx]) = h0;
                    *reinterpret_cast<__half2*>(&sout_h[gidx + 2]) = h1;
                }
                if (sout_f) {
                    float4 so; so.x = s[0]; so.y = s[1]; so.z = s[2]; so.w = s[3];
                    *reinterpret_cast<float4*>(&sout_f[gidx]) = so;
                }
            }
        }
    }
}

// ---------------- launch ----------------
extern "C" void kernel_launch(void* const* d_in, const int* in_sizes, int n_in,
                              void* d_out, int out_size) {
    const float* x  = (const float*)d_in[0];
    const float* W1 = (const float*)d_in[1];
    const float* b1 = (const float*)d_in[2];
    const float* W2 = (const float*)d_in[3];
    const float* b2 = (const float*)d_in[4];
    const float* W3 = (const float*)d_in[5];
    const float* b3 = (const float*)d_in[6];
    float* out = (float*)d_out;

    float *v1, *v2, *v3, *acc1;
    __half *s1, *s2, *a1c, *w1c, *w2c, *w3c;
    cudaGetSymbolAddress((void**)&v1, g_v1);
    cudaGetSymbolAddress((void**)&v2, g_v2);
    cudaGetSymbolAddress((void**)&v3, g_v3);
    cudaGetSymbolAddress((void**)&acc1, g_acc1);
    cudaGetSymbolAddress((void**)&s1, g_s1);
    cudaGetSymbolAddress((void**)&s2, g_s2);
    cudaGetSymbolAddress((void**)&a1c, g_A1c);
    cudaGetSymbolAddress((void**)&w1c, g_W1c);
    cudaGetSymbolAddress((void**)&w2c, g_W2c);
    cudaGetSymbolAddress((void**)&w3c, g_W3c);

    cudaFuncSetAttribute(snn_mma<128>, cudaFuncAttributeMaxDynamicSharedMemorySize, kSmemBytes);
    cudaFuncSetAttribute(snn_mma<64>,  cudaFuncAttributeMaxDynamicSharedMemorySize, kSmemBytes);

    init_state<<<512, 256>>>();
    build_xcat<<<(int)(((long)kB * kLd1) / 256), 256>>>(x);
    build_w1<<<dim3(125, 64), 256>>>(W1);
    pad_w1<<<6400, 256>>>();
    build_w2<<<dim3(64, 64), 256>>>(W2);
    build_w3<<<dim3(64, 32), 256>>>(W3);

    dim3 blk(256);
    dim3 gridH(16, 8);    // N=2048 x M=1024, BM=128
    dim3 gridO(8, 16);    // N=1000 (8 tiles of 128) x M=1024, BM=64 -> 128 CTAs

    for (int t = 0; t < kT; t++) {
        snn_mma<128><<<gridH, blk, kSmemBytes>>>(
            a1c + (long)t * kK1, kLd1, w1c + (long)t * kK1, kLd1, kK1,
            b1, v1, acc1, s1, nullptr, kH);
        snn_mma<128><<<gridH, blk, kSmemBytes>>>(
            s1, kH, w2c, kK2, kK2,
            b2, v2, nullptr, s2, nullptr, kH);
        snn_mma<64><<<gridO, blk, kSmemBytes>>>(
            s2, kH, w3c, kK2, kK2,
            b3, v3, nullptr, nullptr, (t == kT - 1) ? out : nullptr, kO);
    }
}

// round 5
// speedup vs baseline: 5.2130x; 1.0132x over previous
#include <cuda_runtime.h>
#include <cuda_fp16.h>
#include <cstdint>

// SNNModel: 3-layer LIF SNN, T=10. B=1024, D=4000, H=2048, O=1000.
// HMMA (mma.sync m16n8k16, fp16 in / fp32 accum) with split-precision weights:
//   L2/L3: binary spikes exact in fp16; W = Wh+Wl fp16 2-split, K-concat K'=4096.
//   L1: x=xh+xl, W1=wh+wl; 3 cross terms (xh*wh, xh*wl, xl*wh), K'=1280.
// R5: 3-stage cp.async pipeline, 1 barrier/chunk, register-double-buffered ldmatrix.

namespace {
constexpr int kB = 1024, kD = 4000, kH = 2048, kO = 1000, kT = 10;
constexpr int kK1  = 1280;        // per-step padded K' for layer 1 (3*400 -> 1280)
constexpr int kLd1 = kT * kK1;    // 12800
constexpr int kK2  = 2 * kH;      // 4096
constexpr int kOp  = 1024;        // padded N rows for W3cat
}

// ---------------- persistent device buffers ----------------
__device__ __align__(16) float g_v1[kB * kH];
__device__ __align__(16) float g_v2[kB * kH];
__device__ __align__(16) float g_v3[kB * kO];
__device__ __align__(16) float g_acc1[kB * kH];
__device__ __align__(16) __half g_s1[kB * kH];
__device__ __align__(16) __half g_s2[kB * kH];
__device__ __align__(16) __half g_A1c[(size_t)kB * kLd1];   // [B, 10*1280]
__device__ __align__(16) __half g_W1c[(size_t)kH * kLd1];   // [H, 10*1280] (N-major, K contig)
__device__ __align__(16) __half g_W2c[(size_t)kH * kK2];    // [H, 4096]
__device__ __align__(16) __half g_W3c[(size_t)kOp * kK2];   // [1024, 4096]

// ---------------- PTX helpers ----------------
__device__ __forceinline__ uint32_t smem_u32(const void* p) {
    uint32_t a;
    asm("{ .reg .u64 t; cvta.to.shared.u64 t, %1; cvt.u32.u64 %0, t; }" : "=r"(a) : "l"(p));
    return a;
}
__device__ __forceinline__ void cp16(uint32_t dst, const void* src) {
    asm volatile("cp.async.cg.shared.global [%0], [%1], 16;" :: "r"(dst), "l"(src));
}
__device__ __forceinline__ void cp_commit() { asm volatile("cp.async.commit_group;" ::: "memory"); }
__device__ __forceinline__ void cp_wait1()  { asm volatile("cp.async.wait_group 1;" ::: "memory"); }
__device__ __forceinline__ void cp_wait0()  { asm volatile("cp.async.wait_group 0;" ::: "memory"); }
__device__ __forceinline__ void ldmx4(uint32_t& r0, uint32_t& r1, uint32_t& r2, uint32_t& r3,
                                      uint32_t addr) {
    asm volatile("ldmatrix.sync.aligned.m8n8.x4.shared.b16 {%0,%1,%2,%3}, [%4];"
                 : "=r"(r0), "=r"(r1), "=r"(r2), "=r"(r3) : "r"(addr));
}
__device__ __forceinline__ void mma16816(float& c0, float& c1, float& c2, float& c3,
                                         uint32_t a0, uint32_t a1, uint32_t a2, uint32_t a3,
                                         uint32_t b0, uint32_t b1) {
    asm volatile(
        "mma.sync.aligned.m16n8k16.row.col.f32.f16.f16.f32 "
        "{%0,%1,%2,%3}, {%4,%5,%6,%7}, {%8,%9}, {%0,%1,%2,%3};"
        : "+f"(c0), "+f"(c1), "+f"(c2), "+f"(c3)
        : "r"(a0), "r"(a1), "r"(a2), "r"(a3), "r"(b0), "r"(b1));
}
__device__ __forceinline__ uint32_t sw128(uint32_t off) {
    return off ^ ((off >> 3) & 0x70);
}

// ---------------- init / precompute kernels ----------------
__global__ void init_state() {
    int stride = gridDim.x * blockDim.x;
    int i0 = blockIdx.x * blockDim.x + threadIdx.x;
    for (int i = i0; i < kB * kH; i += stride) {
        g_v1[i] = 0.0f; g_v2[i] = 0.0f; g_acc1[i] = 0.0f;
    }
    for (int i = i0; i < kB * kO; i += stride) g_v3[i] = 0.0f;
}

// A1cat[m, t*1280 + j] : j<1200 -> seg=j/400 (0,1: xh; 2: xl) of x[m, t*400 + j%400]; else 0
__global__ void build_xcat(const float* __restrict__ x) {
    long idx = (long)blockIdx.x * blockDim.x + threadIdx.x;
    if (idx >= (long)kB * kLd1) return;
    int m = (int)(idx / kLd1), c = (int)(idx % kLd1);
    int t = c / kK1, j = c % kK1;
    __half o = __float2half_rn(0.0f);
    if (j < 1200) {
        int seg = j / 400, kk = j % 400;
        float xv = x[(long)m * kD + t * 400 + kk];
        __half h = __float2half_rn(xv);
        o = (seg < 2) ? h : __float2half_rn(xv - __half2float(h));
    }
    g_A1c[idx] = o;
}

// W1cat: per step block [wh | wl | wh] (each 400) + 80 pad. Pairs: xh*wh, xh*wl, xl*wh.
__global__ void build_w1(const float* __restrict__ W) {   // W: [4000, 2048]
    __shared__ float tile[32][33];
    int k0 = blockIdx.x * 32, n0 = blockIdx.y * 32;
    int tx = threadIdx.x & 31, ty = threadIdx.x >> 5;
    for (int i = 0; i < 32; i += 8)
        tile[ty + i][tx] = W[(long)(k0 + ty + i) * kH + n0 + tx];
    __syncthreads();
    for (int i = 0; i < 32; i += 8) {
        int n = n0 + ty + i, kg = k0 + tx;
        int t = kg / 400, kk = kg % 400;
        float v = tile[tx][ty + i];
        __half h = __float2half_rn(v);
        __half l = __float2half_rn(v - __half2float(h));
        long base = (long)n * kLd1 + (long)t * kK1;
        g_W1c[base + kk]       = h;
        g_W1c[base + 800 + kk] = h;
        g_W1c[base + 400 + kk] = l;
    }
}
__global__ void pad_w1() {   // zero cols [1200,1280) of every step block
    long idx = (long)blockIdx.x * blockDim.x + threadIdx.x;   // kH * 10 * 80
    if (idx >= (long)kH * 800) return;
    int n = (int)(idx / 800), r = (int)(idx % 800);
    int t = r / 80, j = 1200 + r % 80;
    g_W1c[(long)n * kLd1 + (long)t * kK1 + j] = __float2half_rn(0.0f);
}

__global__ void build_w2(const float* __restrict__ W) {   // [2048,2048] -> [2048, 4096]
    __shared__ float tile[32][33];
    int k0 = blockIdx.x * 32, n0 = blockIdx.y * 32;
    int tx = threadIdx.x & 31, ty = threadIdx.x >> 5;
    for (int i = 0; i < 32; i += 8)
        tile[ty + i][tx] = W[(long)(k0 + ty + i) * kH + n0 + tx];
    __syncthreads();
    for (int i = 0; i < 32; i += 8) {
        int n = n0 + ty + i, k = k0 + tx;
        float v = tile[tx][ty + i];
        __half h = __float2half_rn(v);
        __half l = __float2half_rn(v - __half2float(h));
        long base = (long)n * kK2;
        g_W2c[base + k] = h; g_W2c[base + kH + k] = l;
    }
}

__global__ void build_w3(const float* __restrict__ W) {   // [2048,1000] -> [1024, 4096]
    __shared__ float tile[32][33];
    int k0 = blockIdx.x * 32, n0 = blockIdx.y * 32;
    int tx = threadIdx.x & 31, ty = threadIdx.x >> 5;
    for (int i = 0; i < 32; i += 8) {
        int n = n0 + tx;
        tile[ty + i][tx] = (n < kO) ? W[(long)(k0 + ty + i) * kO + n] : 0.0f;
    }
    __syncthreads();
    for (int i = 0; i < 32; i += 8) {
        int n = n0 + ty + i, k = k0 + tx;
        float v = tile[tx][ty + i];
        __half h = __float2half_rn(v);
        __half l = __float2half_rn(v - __half2float(h));
        long base = (long)n * kK2;
        g_W3c[base + k] = h; g_W3c[base + kH + k] = l;
    }
}

// ---------------- main HMMA GEMM + LIF kernel ----------------
// D[BM x 128] tile = A[m0:,:K'] @ Wc[n0:,:K']^T, A k-index wraps mod 2048.
template <int BM>
__global__ __launch_bounds__(256) void snn_mma(
    const __half* __restrict__ A, long lda,
    const __half* __restrict__ Wc, long ldw,
    int Kp,
    const float* __restrict__ bias,
    float* __restrict__ vstate,
    float* __restrict__ acc,            // nullable (layer-1 running accumulator)
    __half* __restrict__ sout_h,        // nullable
    float* __restrict__ sout_f,         // nullable
    int N)
{
    constexpr int MI = BM / 32;                 // 16-row A blocks per warp
    constexpr uint32_t kABytes = BM * 128;      // A stage bytes
    constexpr uint32_t kStage = kABytes + 16384;

    extern __shared__ __align__(1024) char smem[];
    const uint32_t sbase = smem_u32(smem);
    const int tid = threadIdx.x, wid = tid >> 5, lid = tid & 31;
    const int m0 = blockIdx.y * BM, n0 = blockIdx.x * 128;
    const int wm = (wid >> 2) * (16 * MI);      // warp m offset
    const int wn = (wid & 3) * 32;              // warp n offset

    const int NC = Kp / 64;

    float accf[MI][4][4];
#pragma unroll
    for (int i = 0; i < MI; i++)
#pragma unroll
        for (int j = 0; j < 4; j++)
#pragma unroll
            for (int q = 0; q < 4; q++) accf[i][j][q] = 0.0f;

    auto load_chunk = [&](int c, int b) {
        const int k0 = c * 64;
        const int ak = k0 & 2047;               // A wraps mod 2048 (K-concat reuse)
        const uint32_t abuf = sbase + (uint32_t)b * kStage;
        const uint32_t wbuf = abuf + kABytes;
#pragma unroll
        for (int p = 0; p < MI; p++) {
            int off = (p * 256 + tid) * 16;
            int row = off >> 7, colb = off & 127;
            cp16(abuf + sw128((uint32_t)off), A + (long)(m0 + row) * lda + ak + (colb >> 1));
        }
#pragma unroll
        for (int p = 0; p < 4; p++) {
            int off = (p * 256 + tid) * 16;
            int row = off >> 7, colb = off & 127;
            cp16(wbuf + sw128((uint32_t)off), Wc + (long)(n0 + row) * ldw + k0 + (colb >> 1));
        }
        cp_commit();
    };

    // per-lane ldmatrix address components
    const int a_r = (lid & 7) + ((lid >> 3) & 1) * 8;
    const int a_k = (lid >> 4) * 16;
    const int b_r = (lid & 7) + (lid >> 4) * 8;
    const int b_k = ((lid >> 3) & 1) * 16;

    load_chunk(0, 0);
    load_chunk(1, 1);

    for (int c = 0; c < NC; c++) {
        const int b = c % 3;
        if (c + 1 < NC) cp_wait1(); else cp_wait0();
        __syncthreads();                         // chunk c visible; chunk c-1 reads done
        if (c + 2 < NC) load_chunk(c + 2, (c + 2) % 3);

        const uint32_t abuf = sbase + (uint32_t)b * kStage;
        const uint32_t wbuf = abuf + kABytes;

        uint32_t af[2][MI][4], bfr[2][2][4];
        // prime ks=0
#pragma unroll
        for (int mi = 0; mi < MI; mi++) {
            uint32_t off = (uint32_t)((wm + mi * 16 + a_r) * 128 + a_k);
            ldmx4(af[0][mi][0], af[0][mi][1], af[0][mi][2], af[0][mi][3], abuf + sw128(off));
        }
#pragma unroll
        for (int np = 0; np < 2; np++) {
            uint32_t off = (uint32_t)((wn + np * 16 + b_r) * 128 + b_k);
            ldmx4(bfr[0][np][0], bfr[0][np][1], bfr[0][np][2], bfr[0][np][3], wbuf + sw128(off));
        }

#pragma unroll
        for (int ks = 0; ks < 4; ks++) {
            const int cur = ks & 1, nxt = cur ^ 1;
            if (ks < 3) {
#pragma unroll
                for (int mi = 0; mi < MI; mi++) {
                    uint32_t off = (uint32_t)((wm + mi * 16 + a_r) * 128 + (ks + 1) * 32 + a_k);
                    ldmx4(af[nxt][mi][0], af[nxt][mi][1], af[nxt][mi][2], af[nxt][mi][3],
                          abuf + sw128(off));
                }
#pragma unroll
                for (int np = 0; np < 2; np++) {
                    uint32_t off = (uint32_t)((wn + np * 16 + b_r) * 128 + (ks + 1) * 32 + b_k);
                    ldmx4(bfr[nxt][np][0], bfr[nxt][np][1], bfr[nxt][np][2], bfr[nxt][np][3],
                          wbuf + sw128(off));
                }
            }
#pragma unroll
            for (int mi = 0; mi < MI; mi++)
#pragma unroll
                for (int ni = 0; ni < 4; ni++) {
                    const uint32_t* bp = &bfr[cur][ni >> 1][(ni & 1) * 2];
                    mma16816(accf[mi][ni][0], accf[mi][ni][1], accf[mi][ni][2], accf[mi][ni][3],
                             af[cur][mi][0], af[cur][mi][1], af[cur][mi][2], af[cur][mi][3],
                             bp[0], bp[1]);
                }
        }
    }

    __syncthreads();   // all warps done with stage buffers before epilogue reuse

    // epilogue part 1: accumulators -> smem fp32 [BM][128]
    {
        float* Ds = reinterpret_cast<float*>(smem);
        const int g = lid >> 2, tg = lid & 3;
#pragma unroll
        for (int mi = 0; mi < MI; mi++) {
#pragma unroll
            for (int ni = 0; ni < 4; ni++) {
                int row = wm + mi * 16 + g;
                int col = wn + ni * 8 + tg * 2;
                Ds[row * 128 + col]           = accf[mi][ni][0];
                Ds[row * 128 + col + 1]       = accf[mi][ni][1];
                Ds[(row + 8) * 128 + col]     = accf[mi][ni][2];
                Ds[(row + 8) * 128 + col + 1] = accf[mi][ni][3];
            }
        }
    }
    __syncthreads();

    // epilogue part 2: coalesced LIF RMW
    {
        float* Ds = reinterpret_cast<float*>(smem);
        int ncols = N - n0; if (ncols > 128) ncols = 128;
#pragma unroll 4
        for (int p = 0; p < BM / 8; p++) {
            int i4 = p * 256 + tid;
            int row = i4 >> 5, col = (i4 & 31) * 4;
            if (col < ncols) {
                long gidx = (long)(m0 + row) * N + n0 + col;
                float4 d = *reinterpret_cast<float4*>(&Ds[row * 128 + col]);
                if (acc) {
                    float4 a = *reinterpret_cast<const float4*>(&acc[gidx]);
                    d.x += a.x; d.y += a.y; d.z += a.z; d.w += a.w;
                    *reinterpret_cast<float4*>(&acc[gidx]) = d;
                }
                float4 bb = *reinterpret_cast<const float4*>(&bias[n0 + col]);
                float4 vo = *reinterpret_cast<float4*>(&vstate[gidx]);
                float cc, v, s[4];
                cc = d.x + bb.x; v = vo.x + (cc - vo.x) * 0.5f; s[0] = (v >= 1.0f) ? 1.0f : 0.0f; vo.x = v * (1.0f - s[0]);
                cc = d.y + bb.y; v = vo.y + (cc - vo.y) * 0.5f; s[1] = (v >= 1.0f) ? 1.0f : 0.0f; vo.y = v * (1.0f - s[1]);
                cc = d.z + bb.z; v = vo.z + (cc - vo.z) * 0.5f; s[2] = (v >= 1.0f) ? 1.0f : 0.0f; vo.z = v * (1.0f - s[2]);
                cc = d.w + bb.w; v = vo.w + (cc - vo.w) * 0.5f; s[3] = (v >= 1.0f) ? 1.0f : 0.0f; vo.w = v * (1.0f - s[3]);
                *reinterpret_cast<float4*>(&vstate[gidx]) = vo;
                if (sout_h) {
                    __half2 h0 = __floats2half2_rn(s[0], s[1]);
                    __half2 h1 = __floats2half2_rn(s[2], s[3]);
                    *reinterpret_cast<__half2*>(&sout_h[gidx]) = h0;
                    *reinterpret_cast<__half2*>(&sout_h[gidx + 2]) = h1;
                }
                if (sout_f) {
                    float4 so; so.x = s[0]; so.y = s[1]; so.z = s[2]; so.w = s[3];
                    *reinterpret_cast<float4*>(&sout_f[gidx]) = so;
                }
            }
        }
    }
}

// ---------------- launch ----------------
extern "C" void kernel_launch(void* const* d_in, const int* in_sizes, int n_in,
                              void* d_out, int out_size) {
    const float* x  = (const float*)d_in[0];
    const float* W1 = (const float*)d_in[1];
    const float* b1 = (const float*)d_in[2];
    const float* W2 = (const float*)d_in[3];
    const float* b2 = (const float*)d_in[4];
    const float* W3 = (const float*)d_in[5];
    const float* b3 = (const float*)d_in[6];
    float* out = (float*)d_out;

    float *v1, *v2, *v3, *acc1;
    __half *s1, *s2, *a1c, *w1c, *w2c, *w3c;
    cudaGetSymbolAddress((void**)&v1, g_v1);
    cudaGetSymbolAddress((void**)&v2, g_v2);
    cudaGetSymbolAddress((void**)&v3, g_v3);
    cudaGetSymbolAddress((void**)&acc1, g_acc1);
    cudaGetSymbolAddress((void**)&s1, g_s1);
    cudaGetSymbolAddress((void**)&s2, g_s2);
    cudaGetSymbolAddress((void**)&a1c, g_A1c);
    cudaGetSymbolAddress((void**)&w1c, g_W1c);
    cudaGetSymbolAddress((void**)&w2c, g_W2c);
    cudaGetSymbolAddress((void**)&w3c, g_W3c);

    constexpr unsigned kSmem128 = 3u * (128u * 128u + 16384u);   // 98304
    constexpr unsigned kSmem64  = 3u * (64u * 128u + 16384u);    // 73728
    cudaFuncSetAttribute(snn_mma<128>, cudaFuncAttributeMaxDynamicSharedMemorySize, kSmem128);
    cudaFuncSetAttribute(snn_mma<64>,  cudaFuncAttributeMaxDynamicSharedMemorySize, kSmem64);

    init_state<<<512, 256>>>();
    build_xcat<<<(int)(((long)kB * kLd1) / 256), 256>>>(x);
    build_w1<<<dim3(125, 64), 256>>>(W1);
    pad_w1<<<6400, 256>>>();
    build_w2<<<dim3(64, 64), 256>>>(W2);
    build_w3<<<dim3(64, 32), 256>>>(W3);

    dim3 blk(256);
    dim3 gridH(16, 8);    // N=2048 x M=1024, BM=128
    dim3 gridO(8, 16);    // N=1000 (8 tiles of 128) x M=1024, BM=64 -> 128 CTAs

    for (int t = 0; t < kT; t++) {
        snn_mma<128><<<gridH, blk, kSmem128>>>(
            a1c + (long)t * kK1, kLd1, w1c + (long)t * kK1, kLd1, kK1,
            b1, v1, acc1, s1, nullptr, kH);
        snn_mma<128><<<gridH, blk, kSmem128>>>(
            s1, kH, w2c, kK2, kK2,
            b2, v2, nullptr, s2, nullptr, kH);
        snn_mma<64><<<gridO, blk, kSmem64>>>(
            s2, kH, w3c, kK2, kK2,
            b3, v3, nullptr, nullptr, (t == kT - 1) ? out : nullptr, kO);
    }
}